// round 13
// baseline (speedup 1.0000x reference)
#include <cuda_runtime.h>
#include <cuda_bf16.h>
#include <cstdint>

#define NBATCH   2048
#define CEM_S    1000
#define CEM_NE   100
#define CEM_NI   10
#define HID      128
#define TOTAL    (NBATCH * CEM_S)     // 2,048,000
#define INIT_SIG 10.0f

// ---------------- device scratch (no allocations allowed) ----------------
__device__ float g_mu[NBATCH];
__device__ float g_sigma[NBATCH];
__device__ float g_y[TOTAL];
__device__ float g_fx[TOTAL];
// W2 in mma-fragment order: [s:8][jt:16][lane:32] -> (bh0, bh1, bl0, bl1)
__device__ __align__(16) uint4 g_Bfrag[8 * 16 * 32];

// ---------------- threefry-2x32 (exact JAX, partitionable mode) ----------------
static __host__ __device__ __forceinline__ uint32_t rotl32(uint32_t v, uint32_t d) {
    return (v << d) | (v >> (32u - d));
}

static __host__ __device__ __forceinline__ void threefry2x32(
    uint32_t k0, uint32_t k1, uint32_t& x0, uint32_t& x1)
{
    uint32_t ks0 = k0, ks1 = k1, ks2 = k0 ^ k1 ^ 0x1BD11BDAu;
    x0 += ks0; x1 += ks1;
#define TF_R(r) { x0 += x1; x1 = rotl32(x1, r); x1 ^= x0; }
    TF_R(13) TF_R(15) TF_R(26) TF_R(6)   x0 += ks1; x1 += ks2 + 1u;
    TF_R(17) TF_R(29) TF_R(16) TF_R(24)  x0 += ks2; x1 += ks0 + 2u;
    TF_R(13) TF_R(15) TF_R(26) TF_R(6)   x0 += ks0; x1 += ks1 + 3u;
    TF_R(17) TF_R(29) TF_R(16) TF_R(24)  x0 += ks1; x1 += ks2 + 4u;
    TF_R(13) TF_R(15) TF_R(26) TF_R(6)   x0 += ks2; x1 += ks0 + 5u;
#undef TF_R
}

__device__ __forceinline__ uint32_t tf_bits32(uint32_t k0, uint32_t k1, uint32_t idx) {
    uint32_t x0 = 0u, x1 = idx;
    threefry2x32(k0, k1, x0, x1);
    return x0 ^ x1;
}

__device__ __forceinline__ float bits_to_normal(uint32_t bits) {
    float f = __uint_as_float((bits >> 9) | 0x3f800000u) - 1.0f;   // [0,1)
    const float lo = -0.99999994f;
    float u = fmaxf(lo, f * 2.0f + lo);
    float w = -log1pf(-u * u);
    float p;
    if (w < 5.0f) {
        w -= 2.5f;
        p = 2.81022636e-08f;
        p = fmaf(p, w, 3.43273939e-07f);
        p = fmaf(p, w, -3.5233877e-06f);
        p = fmaf(p, w, -4.39150654e-06f);
        p = fmaf(p, w, 0.00021858087f);
        p = fmaf(p, w, -0.00125372503f);
        p = fmaf(p, w, -0.00417768164f);
        p = fmaf(p, w, 0.246640727f);
        p = fmaf(p, w, 1.50140941f);
    } else {
        w = sqrtf(w) - 3.0f;
        p = -0.000200214257f;
        p = fmaf(p, w, 0.000100950558f);
        p = fmaf(p, w, 0.00134934322f);
        p = fmaf(p, w, -0.00367342844f);
        p = fmaf(p, w, 0.00573950773f);
        p = fmaf(p, w, -0.0076224613f);
        p = fmaf(p, w, 0.00943887047f);
        p = fmaf(p, w, 1.00167406f);
        p = fmaf(p, w, 2.83297682f);
    }
    return 1.4142135623730951f * (p * u);
}

// ---------------- fast tanh: 1 - 2/(e^{2x}+1), MUFU ex2 + rcp ----------------
__device__ __forceinline__ float tanh_fast(float x) {
    float m = x * 2.8853900817779268f;   // 2 * log2(e)
    float e;
    asm("ex2.approx.f32 %0, %1;" : "=f"(e) : "f"(m));
    float den = e + 1.0f;
    float r;
    asm("rcp.approx.f32 %0, %1;" : "=f"(r) : "f"(den));
    return fmaf(-2.0f, r, 1.0f);
}

// ---------------- bf16 mma helper ----------------
__device__ __forceinline__ void mma_bf16(float* d, const uint32_t* a, uint32_t b0, uint32_t b1) {
    asm volatile(
        "mma.sync.aligned.m16n8k16.row.col.f32.bf16.bf16.f32 "
        "{%0,%1,%2,%3}, {%4,%5,%6,%7}, {%8,%9}, {%0,%1,%2,%3};"
        : "+f"(d[0]), "+f"(d[1]), "+f"(d[2]), "+f"(d[3])
        : "r"(a[0]), "r"(a[1]), "r"(a[2]), "r"(a[3]), "r"(b0), "r"(b1));
}

// compute h1 at k and k+1; emit packed bf16 hi-pair (lo half = k) and lo-pair.
// cvt.rn.bf16x2.f32 d,a,b : d.hi=cvt(a), d.lo=cvt(b) -- .rn matches __float2bfloat16.
__device__ __forceinline__ void h1pair(
    float x, float y, int k,
    const float* sW1a, const float* sW1b, const float* sb1,
    uint32_t& ah, uint32_t& al)
{
    float v0 = tanh_fast(fmaf(x, sW1a[k],     fmaf(y, sW1b[k],     sb1[k])));
    float v1 = tanh_fast(fmaf(x, sW1a[k + 1], fmaf(y, sW1b[k + 1], sb1[k + 1])));
    asm("cvt.rn.bf16x2.f32 %0, %1, %2;" : "=r"(ah) : "f"(v1), "f"(v0));
    float h0 = __uint_as_float(ah << 16);
    float h1 = __uint_as_float(ah & 0xFFFF0000u);
    float l0 = v0 - h0;
    float l1 = v1 - h1;
    asm("cvt.rn.bf16x2.f32 %0, %1, %2;" : "=r"(al) : "f"(l1), "f"(l0));
}

// ---------------- prep: W2 -> fragment-ordered hi/lo uint4 image ----------------
// thread i -> (s, jt, lane): lane=(qr,qc); j = jt*8+qr; kb = 16s + 2qc.
// bh0 = hi(W2[kb][j], W2[kb+1][j]); bh1 = hi(k+8); bl0/bl1 = lo parts.
__global__ void w2prep_kernel(const float* __restrict__ W2) {
    int i = blockIdx.x * blockDim.x + threadIdx.x;
    if (i >= 8 * 16 * 32) return;
    int lane = i & 31, jt = (i >> 5) & 15, s = i >> 9;
    int qr = lane >> 2, qc = lane & 3;
    int j  = jt * 8 + qr;
    int kb = s * 16 + qc * 2;

    float v[4] = { W2[kb * 128 + j],       W2[(kb + 1) * 128 + j],
                   W2[(kb + 8) * 128 + j], W2[(kb + 9) * 128 + j] };
    uint32_t hw[4], lw[4];
#pragma unroll
    for (int t = 0; t < 4; t++) {
        __nv_bfloat16 hb = __float2bfloat16(v[t]);
        __nv_bfloat16 lb = __float2bfloat16(v[t] - __bfloat162float(hb));
        hw[t] = (uint32_t)__bfloat16_as_ushort(hb);
        lw[t] = (uint32_t)__bfloat16_as_ushort(lb);
    }
    uint4 f;
    f.x = hw[0] | (hw[1] << 16);   // bh0 : k = kb, kb+1
    f.y = hw[2] | (hw[3] << 16);   // bh1 : k = kb+8, kb+9
    f.z = lw[0] | (lw[1] << 16);   // bl0
    f.w = lw[2] | (lw[3] << 16);   // bl1
    g_Bfrag[i] = f;
}

// ---------------- init ----------------
__global__ void init_kernel() {
    int i = blockIdx.x * blockDim.x + threadIdx.x;
    if (i < NBATCH) { g_mu[i] = 0.0f; g_sigma[i] = INIT_SIG; }
}

// ---------------- fused sample + energy kernel (mma.sync bf16 3-term split) ----------------
// One block = 128 candidates. 256 threads (8 warps), 2 CTAs/SM.
// B fragments pre-packed per lane: 1 LDS.128 per (s, jt) replaces 4 LDS.32.
__global__ void __launch_bounds__(256, 2) energy_kernel(
    uint32_t k0, uint32_t k1,
    const float* __restrict__ x,  const float* __restrict__ W1, const float* __restrict__ b1,
    const float* __restrict__ b2, const float* __restrict__ W3, const float* __restrict__ b3)
{
    extern __shared__ uint4 bfrag[];     // [8*16*32] = 64KB

    __shared__ float sy[128], sxv[128];
    __shared__ float sW1a[HID], sW1b[HID], sb1[HID], sb2[HID], sW3[HID];
    __shared__ float sb3;

    const int tid  = threadIdx.x;
    const int w    = tid >> 5;
    const int lane = tid & 31;
    const int g0   = blockIdx.x * 128;

    // stage fragment image (linear uint4 copy, 4096 entries)
#pragma unroll
    for (int i = tid; i < 8 * 16 * 32; i += 256) bfrag[i] = g_Bfrag[i];

    // stage small weights
    if (tid < HID) {
        sW1a[tid] = W1[tid];
        sW1b[tid] = W1[HID + tid];
        sb1[tid]  = b1[tid];
        sb2[tid]  = b2[tid];
        sW3[tid]  = W3[tid];
    }
    if (tid == 0) sb3 = b3[0];

    // candidates: eps via threefry (partitionable), Ys = mu + sigma*eps
    if (tid < 128) {
        int g = g0 + tid;
        int b = g / CEM_S;
        float eps = bits_to_normal(tf_bits32(k0, k1, (uint32_t)g));
        float yv  = g_mu[b] + g_sigma[b] * eps;
        sy[tid]  = yv;
        sxv[tid] = x[b];
        g_y[g]   = yv;
    }
    __syncthreads();

    // fragment coordinates
    const int qr = lane >> 2;       // 0..7
    const int qc = lane & 3;        // 0..3
    const int mr = 16 * w + qr;     // rows mr, mr+8
    const float x0v = sxv[mr],     y0v = sy[mr];
    const float x1v = sxv[mr + 8], y1v = sy[mr + 8];

    float acc[16][4];
#pragma unroll
    for (int jt = 0; jt < 16; jt++)
#pragma unroll
        for (int c = 0; c < 4; c++) acc[jt][c] = 0.0f;

#pragma unroll
    for (int s = 0; s < 8; s++) {
        const int kb = 16 * s + qc * 2;

        // A fragments (hi & lo), computed in registers
        uint32_t ah[4], al[4];
        h1pair(x0v, y0v, kb,     sW1a, sW1b, sb1, ah[0], al[0]);   // (r,   c..c+1)
        h1pair(x1v, y1v, kb,     sW1a, sW1b, sb1, ah[1], al[1]);   // (r+8, c..c+1)
        h1pair(x0v, y0v, kb + 8, sW1a, sW1b, sb1, ah[2], al[2]);   // (r,   c+8..c+9)
        h1pair(x1v, y1v, kb + 8, sW1a, sW1b, sb1, ah[3], al[3]);   // (r+8, c+8..c+9)

        const uint4* srow = bfrag + (s << 9) + lane;   // [s][jt][lane]
#pragma unroll
        for (int jt = 0; jt < 16; jt++) {
            uint4 f = srow[jt << 5];
            mma_bf16(acc[jt], ah, f.x, f.y);   // Ah * Bh
            mma_bf16(acc[jt], al, f.x, f.y);   // Al * Bh
            mma_bf16(acc[jt], ah, f.z, f.w);   // Ah * Bl
        }
    }

    // epilogue: h2 = tanh(c + b2); E = sum_j h2*W3 + b3; fx = E^2
    float s0 = 0.0f, s1 = 0.0f;   // rows mr, mr+8
#pragma unroll
    for (int jt = 0; jt < 16; jt++) {
        const int j0 = jt * 8 + qc * 2;
        float b2a = sb2[j0], b2b = sb2[j0 + 1];
        float w3a = sW3[j0], w3b = sW3[j0 + 1];
        s0 = fmaf(tanh_fast(acc[jt][0] + b2a), w3a, s0);
        s0 = fmaf(tanh_fast(acc[jt][1] + b2b), w3b, s0);
        s1 = fmaf(tanh_fast(acc[jt][2] + b2a), w3a, s1);
        s1 = fmaf(tanh_fast(acc[jt][3] + b2b), w3b, s1);
    }
    // quad reduction over qc (lanes differing in bits 0,1)
    s0 += __shfl_xor_sync(0xffffffffu, s0, 1);
    s0 += __shfl_xor_sync(0xffffffffu, s0, 2);
    s1 += __shfl_xor_sync(0xffffffffu, s1, 1);
    s1 += __shfl_xor_sync(0xffffffffu, s1, 2);
    if (qc == 0) {
        float e0 = s0 + sb3;
        float e1 = s1 + sb3;
        g_fx[g0 + mr]     = e0 * e0;
        g_fx[g0 + mr + 8] = e1 * e1;
    }
}

// ---------------- per-row top-100 via MSB radix-select (exact top_k semantics) ----------------
__device__ __forceinline__ float block_reduce_256(float v, float* sred) {
    __syncthreads();
    const unsigned mask = 0xffffffffu;
#pragma unroll
    for (int o = 16; o > 0; o >>= 1) v += __shfl_down_sync(mask, v, o);
    int lane = threadIdx.x & 31, w = threadIdx.x >> 5;
    if (lane == 0) sred[w] = v;
    __syncthreads();
    if (w == 0) {
        float r = (lane < 8) ? sred[lane] : 0.0f;
#pragma unroll
        for (int o = 4; o > 0; o >>= 1) r += __shfl_down_sync(mask, r, o);
        if (lane == 0) sred[8] = r;
    }
    __syncthreads();
    return sred[8];
}

__global__ void __launch_bounds__(256) topk_kernel() {
    __shared__ unsigned int sc[256];
    __shared__ unsigned int sh_dig, sh_below;
    __shared__ float sredf[9];
    __shared__ float smu;

    const int tid = threadIdx.x;
    const int b   = blockIdx.x;
    const float* fx = g_fx + (size_t)b * CEM_S;
    const float* yy = g_y  + (size_t)b * CEM_S;

    unsigned int uk[4];
    float yv[4];
    const int i0 = tid * 4;
#pragma unroll
    for (int e = 0; e < 4; e++) {
        int i = i0 + e;
        if (i < CEM_S) { uk[e] = __float_as_uint(fx[i]); yv[e] = yy[i]; }
        else           { uk[e] = 0xFFFFFFFFu; yv[e] = 0.0f; }   // padding > any finite key
    }

    unsigned int pref = 0;
    int kRem = CEM_NE;

#pragma unroll
    for (int p = 24; p >= 0; p -= 8) {
        sc[tid] = 0u;
        __syncthreads();
#pragma unroll
        for (int e = 0; e < 4; e++) {
            bool act = (p == 24) || ((uk[e] >> (p + 8)) == pref);
            if (act) atomicAdd(&sc[(uk[e] >> p) & 0xFFu], 1u);
        }
        __syncthreads();
        for (int off = 1; off < 256; off <<= 1) {
            unsigned int add = (tid >= off) ? sc[tid - off] : 0u;
            __syncthreads();
            sc[tid] += add;
            __syncthreads();
        }
        unsigned int cum  = sc[tid];
        unsigned int prev = (tid == 0) ? 0u : sc[tid - 1];
        if (cum >= (unsigned)kRem && prev < (unsigned)kRem) { sh_dig = (unsigned)tid; sh_below = prev; }
        __syncthreads();
        pref = (pref << 8) | sh_dig;
        kRem -= (int)sh_below;
        __syncthreads();
    }
    const unsigned int T = pref;
    const int r = kRem;

    unsigned int eqc = 0;
#pragma unroll
    for (int e = 0; e < 4; e++) eqc += (uk[e] == T);
    sc[tid] = eqc;
    __syncthreads();
    for (int off = 1; off < 256; off <<= 1) {
        unsigned int add = (tid >= off) ? sc[tid - off] : 0u;
        __syncthreads();
        sc[tid] += add;
        __syncthreads();
    }
    const unsigned int baseEq = sc[tid] - eqc;

    float sum = 0.0f;
    {
        unsigned int o = 0;
#pragma unroll
        for (int e = 0; e < 4; e++) {
            bool isEq = (uk[e] == T);
            bool sel  = (uk[e] < T) || (isEq && (baseEq + o) < (unsigned)r);
            if (isEq) o++;
            if (sel) sum += yv[e];
        }
    }
    float tot = block_reduce_256(sum, sredf);
    if (tid == 0) smu = tot / (float)CEM_NE;
    __syncthreads();
    const float mu = smu;

    float ss = 0.0f;
    {
        unsigned int o = 0;
#pragma unroll
        for (int e = 0; e < 4; e++) {
            bool isEq = (uk[e] == T);
            bool sel  = (uk[e] < T) || (isEq && (baseEq + o) < (unsigned)r);
            if (isEq) o++;
            if (sel) { float d = yv[e] - mu; ss = fmaf(d, d, ss); }
        }
    }
    float sst = block_reduce_256(ss, sredf);
    if (tid == 0) {
        g_mu[b]    = mu;
        g_sigma[b] = sqrtf(sst / (float)CEM_NE);
    }
}

// ---------------- final: yhat + diag-Gaussian samples ----------------
__global__ void sample_kernel(uint32_t k0, uint32_t k1, float* __restrict__ out) {
    int gid = blockIdx.x * blockDim.x + threadIdx.x;
    if (gid >= TOTAL) return;
    int b = gid & (NBATCH - 1);
    float eps = bits_to_normal(tf_bits32(k0, k1, (uint32_t)gid));
    float mu = g_mu[b], sg = g_sigma[b];
    float cov = sg * sg;
    cov = fminf(fmaxf(cov, 1e-3f), 100.0f);
    out[NBATCH + gid] = mu + sqrtf(cov) * eps;
    if (gid < NBATCH) out[gid] = g_mu[gid];
}

// ---------------- launch ----------------
extern "C" void kernel_launch(void* const* d_in, const int* in_sizes, int n_in,
                              void* d_out, int out_size)
{
    const float* x  = (const float*)d_in[0];
    const float* W1 = (const float*)d_in[1];
    const float* b1 = (const float*)d_in[2];
    const float* W2 = (const float*)d_in[3];
    const float* b2 = (const float*)d_in[4];
    const float* W3 = (const float*)d_in[5];
    const float* b3 = (const float*)d_in[6];
    float* out = (float*)d_out;

    // JAX partitionable-mode key derivation
    uint32_t cem0 = 0u, cem1 = 0u; threefry2x32(0u, 42u, cem0, cem1);   // split(key,2)[0]
    uint32_t smp0 = 0u, smp1 = 1u; threefry2x32(0u, 42u, smp0, smp1);   // split(key,2)[1]

    uint32_t ik0[CEM_NI], ik1[CEM_NI];
    for (int i = 0; i < CEM_NI; i++) {
        uint32_t a = 0u, c = (uint32_t)i;
        threefry2x32(cem0, cem1, a, c);
        ik0[i] = a; ik1[i] = c;
    }

    const int SMEM_BYTES = 8 * 16 * 32 * (int)sizeof(uint4);   // 65,536 B
    cudaFuncSetAttribute(energy_kernel, cudaFuncAttributeMaxDynamicSharedMemorySize, SMEM_BYTES);

    w2prep_kernel<<<(8 * 16 * 32 + 255) / 256, 256>>>(W2);
    init_kernel<<<(NBATCH + 255) / 256, 256>>>();

    for (int i = 0; i < CEM_NI; i++) {
        energy_kernel<<<TOTAL / 128, 256, SMEM_BYTES>>>(ik0[i], ik1[i], x, W1, b1, b2, W3, b3);
        topk_kernel<<<NBATCH, 256>>>();
    }

    sample_kernel<<<(TOTAL + 255) / 256, 256>>>(smp0, smp1, out);
}

// round 14
// speedup vs baseline: 1.0007x; 1.0007x over previous
#include <cuda_runtime.h>
#include <cuda_bf16.h>
#include <cstdint>

#define NBATCH   2048
#define CEM_S    1000
#define CEM_NE   100
#define CEM_NI   10
#define HID      128
#define TOTAL    (NBATCH * CEM_S)     // 2,048,000
#define INIT_SIG 10.0f

// ---------------- device scratch (no allocations allowed) ----------------
__device__ float g_mu[NBATCH];
__device__ float g_sigma[NBATCH];
__device__ float g_y[TOTAL];
__device__ float g_fx[TOTAL];
// W2 in mma-fragment order: [s:8][jt:16][lane:32] -> (bh0, bh1, bl0, bl1)
__device__ __align__(16) uint4 g_Bfrag[8 * 16 * 32];

// ---------------- threefry-2x32 (exact JAX, partitionable mode) ----------------
static __host__ __device__ __forceinline__ uint32_t rotl32(uint32_t v, uint32_t d) {
    return (v << d) | (v >> (32u - d));
}

static __host__ __device__ __forceinline__ void threefry2x32(
    uint32_t k0, uint32_t k1, uint32_t& x0, uint32_t& x1)
{
    uint32_t ks0 = k0, ks1 = k1, ks2 = k0 ^ k1 ^ 0x1BD11BDAu;
    x0 += ks0; x1 += ks1;
#define TF_R(r) { x0 += x1; x1 = rotl32(x1, r); x1 ^= x0; }
    TF_R(13) TF_R(15) TF_R(26) TF_R(6)   x0 += ks1; x1 += ks2 + 1u;
    TF_R(17) TF_R(29) TF_R(16) TF_R(24)  x0 += ks2; x1 += ks0 + 2u;
    TF_R(13) TF_R(15) TF_R(26) TF_R(6)   x0 += ks0; x1 += ks1 + 3u;
    TF_R(17) TF_R(29) TF_R(16) TF_R(24)  x0 += ks1; x1 += ks2 + 4u;
    TF_R(13) TF_R(15) TF_R(26) TF_R(6)   x0 += ks2; x1 += ks0 + 5u;
#undef TF_R
}

__device__ __forceinline__ uint32_t tf_bits32(uint32_t k0, uint32_t k1, uint32_t idx) {
    uint32_t x0 = 0u, x1 = idx;
    threefry2x32(k0, k1, x0, x1);
    return x0 ^ x1;
}

__device__ __forceinline__ float bits_to_normal(uint32_t bits) {
    float f = __uint_as_float((bits >> 9) | 0x3f800000u) - 1.0f;   // [0,1)
    const float lo = -0.99999994f;
    float u = fmaxf(lo, f * 2.0f + lo);
    float w = -log1pf(-u * u);
    float p;
    if (w < 5.0f) {
        w -= 2.5f;
        p = 2.81022636e-08f;
        p = fmaf(p, w, 3.43273939e-07f);
        p = fmaf(p, w, -3.5233877e-06f);
        p = fmaf(p, w, -4.39150654e-06f);
        p = fmaf(p, w, 0.00021858087f);
        p = fmaf(p, w, -0.00125372503f);
        p = fmaf(p, w, -0.00417768164f);
        p = fmaf(p, w, 0.246640727f);
        p = fmaf(p, w, 1.50140941f);
    } else {
        w = sqrtf(w) - 3.0f;
        p = -0.000200214257f;
        p = fmaf(p, w, 0.000100950558f);
        p = fmaf(p, w, 0.00134934322f);
        p = fmaf(p, w, -0.00367342844f);
        p = fmaf(p, w, 0.00573950773f);
        p = fmaf(p, w, -0.0076224613f);
        p = fmaf(p, w, 0.00943887047f);
        p = fmaf(p, w, 1.00167406f);
        p = fmaf(p, w, 2.83297682f);
    }
    return 1.4142135623730951f * (p * u);
}

// ---------------- fast tanh: 1 - 2/(e^{2x}+1), MUFU ex2 + rcp ----------------
__device__ __forceinline__ float tanh_fast(float x) {
    float m = x * 2.8853900817779268f;   // 2 * log2(e)
    float e;
    asm("ex2.approx.f32 %0, %1;" : "=f"(e) : "f"(m));
    float den = e + 1.0f;
    float r;
    asm("rcp.approx.f32 %0, %1;" : "=f"(r) : "f"(den));
    return fmaf(-2.0f, r, 1.0f);
}

// ---------------- bf16 mma helper ----------------
__device__ __forceinline__ void mma_bf16(float* d, const uint32_t* a, uint32_t b0, uint32_t b1) {
    asm volatile(
        "mma.sync.aligned.m16n8k16.row.col.f32.bf16.bf16.f32 "
        "{%0,%1,%2,%3}, {%4,%5,%6,%7}, {%8,%9}, {%0,%1,%2,%3};"
        : "+f"(d[0]), "+f"(d[1]), "+f"(d[2]), "+f"(d[3])
        : "r"(a[0]), "r"(a[1]), "r"(a[2]), "r"(a[3]), "r"(b0), "r"(b1));
}

// compute h1 at k and k+1; emit packed bf16 hi-pair (lo half = k) and lo-pair.
// cvt.rn.bf16x2.f32 d,a,b : d.hi=cvt(a), d.lo=cvt(b) -- .rn matches __float2bfloat16.
__device__ __forceinline__ void h1pair(
    float x, float y, int k,
    const float* sW1a, const float* sW1b, const float* sb1,
    uint32_t& ah, uint32_t& al)
{
    float v0 = tanh_fast(fmaf(x, sW1a[k],     fmaf(y, sW1b[k],     sb1[k])));
    float v1 = tanh_fast(fmaf(x, sW1a[k + 1], fmaf(y, sW1b[k + 1], sb1[k + 1])));
    asm("cvt.rn.bf16x2.f32 %0, %1, %2;" : "=r"(ah) : "f"(v1), "f"(v0));
    float h0 = __uint_as_float(ah << 16);
    float h1 = __uint_as_float(ah & 0xFFFF0000u);
    float l0 = v0 - h0;
    float l1 = v1 - h1;
    asm("cvt.rn.bf16x2.f32 %0, %1, %2;" : "=r"(al) : "f"(l1), "f"(l0));
}

// ---------------- prep: W2 -> fragment-ordered hi/lo uint4 image ----------------
// thread i -> (s, jt, lane): lane=(qr,qc); j = jt*8+qr; kb = 16s + 2qc.
// bh0 = hi(W2[kb][j], W2[kb+1][j]); bh1 = hi(k+8); bl0/bl1 = lo parts.
__global__ void w2prep_kernel(const float* __restrict__ W2) {
    int i = blockIdx.x * blockDim.x + threadIdx.x;
    if (i >= 8 * 16 * 32) return;
    int lane = i & 31, jt = (i >> 5) & 15, s = i >> 9;
    int qr = lane >> 2, qc = lane & 3;
    int j  = jt * 8 + qr;
    int kb = s * 16 + qc * 2;

    float v[4] = { W2[kb * 128 + j],       W2[(kb + 1) * 128 + j],
                   W2[(kb + 8) * 128 + j], W2[(kb + 9) * 128 + j] };
    uint32_t hw[4], lw[4];
#pragma unroll
    for (int t = 0; t < 4; t++) {
        __nv_bfloat16 hb = __float2bfloat16(v[t]);
        __nv_bfloat16 lb = __float2bfloat16(v[t] - __bfloat162float(hb));
        hw[t] = (uint32_t)__bfloat16_as_ushort(hb);
        lw[t] = (uint32_t)__bfloat16_as_ushort(lb);
    }
    uint4 f;
    f.x = hw[0] | (hw[1] << 16);   // bh0 : k = kb, kb+1
    f.y = hw[2] | (hw[3] << 16);   // bh1 : k = kb+8, kb+9
    f.z = lw[0] | (lw[1] << 16);   // bl0
    f.w = lw[2] | (lw[3] << 16);   // bl1
    g_Bfrag[i] = f;
}

// ---------------- init ----------------
__global__ void init_kernel() {
    int i = blockIdx.x * blockDim.x + threadIdx.x;
    if (i < NBATCH) { g_mu[i] = 0.0f; g_sigma[i] = INIT_SIG; }
}

// ---------------- fused sample + energy kernel (mma.sync bf16 3-term split) ----------------
// One block = 128 candidates. 256 threads (8 warps), 2 CTAs/SM.
// B fragments pre-packed per lane: 1 LDS.128 per (s, jt) replaces 4 LDS.32.
__global__ void __launch_bounds__(256, 2) energy_kernel(
    uint32_t k0, uint32_t k1,
    const float* __restrict__ x,  const float* __restrict__ W1, const float* __restrict__ b1,
    const float* __restrict__ b2, const float* __restrict__ W3, const float* __restrict__ b3)
{
    extern __shared__ uint4 bfrag[];     // [8*16*32] = 64KB

    __shared__ float sy[128], sxv[128];
    __shared__ float sW1a[HID], sW1b[HID], sb1[HID], sb2[HID], sW3[HID];
    __shared__ float sb3;

    const int tid  = threadIdx.x;
    const int w    = tid >> 5;
    const int lane = tid & 31;
    const int g0   = blockIdx.x * 128;

    // stage fragment image (linear uint4 copy, 4096 entries)
#pragma unroll
    for (int i = tid; i < 8 * 16 * 32; i += 256) bfrag[i] = g_Bfrag[i];

    // stage small weights
    if (tid < HID) {
        sW1a[tid] = W1[tid];
        sW1b[tid] = W1[HID + tid];
        sb1[tid]  = b1[tid];
        sb2[tid]  = b2[tid];
        sW3[tid]  = W3[tid];
    }
    if (tid == 0) sb3 = b3[0];

    // candidates: eps via threefry (partitionable), Ys = mu + sigma*eps
    if (tid < 128) {
        int g = g0 + tid;
        int b = g / CEM_S;
        float eps = bits_to_normal(tf_bits32(k0, k1, (uint32_t)g));
        float yv  = g_mu[b] + g_sigma[b] * eps;
        sy[tid]  = yv;
        sxv[tid] = x[b];
        g_y[g]   = yv;
    }
    __syncthreads();

    // fragment coordinates
    const int qr = lane >> 2;       // 0..7
    const int qc = lane & 3;        // 0..3
    const int mr = 16 * w + qr;     // rows mr, mr+8
    const float x0v = sxv[mr],     y0v = sy[mr];
    const float x1v = sxv[mr + 8], y1v = sy[mr + 8];

    float acc[16][4];
#pragma unroll
    for (int jt = 0; jt < 16; jt++)
#pragma unroll
        for (int c = 0; c < 4; c++) acc[jt][c] = 0.0f;

#pragma unroll
    for (int s = 0; s < 8; s++) {
        const int kb = 16 * s + qc * 2;

        // A fragments (hi & lo), computed in registers
        uint32_t ah[4], al[4];
        h1pair(x0v, y0v, kb,     sW1a, sW1b, sb1, ah[0], al[0]);   // (r,   c..c+1)
        h1pair(x1v, y1v, kb,     sW1a, sW1b, sb1, ah[1], al[1]);   // (r+8, c..c+1)
        h1pair(x0v, y0v, kb + 8, sW1a, sW1b, sb1, ah[2], al[2]);   // (r,   c+8..c+9)
        h1pair(x1v, y1v, kb + 8, sW1a, sW1b, sb1, ah[3], al[3]);   // (r+8, c+8..c+9)

        const uint4* srow = bfrag + (s << 9) + lane;   // [s][jt][lane]
#pragma unroll
        for (int jt = 0; jt < 16; jt++) {
            uint4 f = srow[jt << 5];
            mma_bf16(acc[jt], ah, f.x, f.y);   // Ah * Bh
            mma_bf16(acc[jt], al, f.x, f.y);   // Al * Bh
            mma_bf16(acc[jt], ah, f.z, f.w);   // Ah * Bl
        }
    }

    // epilogue: h2 = tanh(c + b2); E = sum_j h2*W3 + b3; fx = E^2
    float s0 = 0.0f, s1 = 0.0f;   // rows mr, mr+8
#pragma unroll
    for (int jt = 0; jt < 16; jt++) {
        const int j0 = jt * 8 + qc * 2;
        float b2a = sb2[j0], b2b = sb2[j0 + 1];
        float w3a = sW3[j0], w3b = sW3[j0 + 1];
        s0 = fmaf(tanh_fast(acc[jt][0] + b2a), w3a, s0);
        s0 = fmaf(tanh_fast(acc[jt][1] + b2b), w3b, s0);
        s1 = fmaf(tanh_fast(acc[jt][2] + b2a), w3a, s1);
        s1 = fmaf(tanh_fast(acc[jt][3] + b2b), w3b, s1);
    }
    // quad reduction over qc (lanes differing in bits 0,1)
    s0 += __shfl_xor_sync(0xffffffffu, s0, 1);
    s0 += __shfl_xor_sync(0xffffffffu, s0, 2);
    s1 += __shfl_xor_sync(0xffffffffu, s1, 1);
    s1 += __shfl_xor_sync(0xffffffffu, s1, 2);
    if (qc == 0) {
        float e0 = s0 + sb3;
        float e1 = s1 + sb3;
        g_fx[g0 + mr]     = e0 * e0;
        g_fx[g0 + mr + 8] = e1 * e1;
    }
}

// ---------------- per-row top-100 via MSB radix-select (exact top_k semantics) ----------------
__device__ __forceinline__ float block_reduce_256(float v, float* sred) {
    __syncthreads();
    const unsigned mask = 0xffffffffu;
#pragma unroll
    for (int o = 16; o > 0; o >>= 1) v += __shfl_down_sync(mask, v, o);
    int lane = threadIdx.x & 31, w = threadIdx.x >> 5;
    if (lane == 0) sred[w] = v;
    __syncthreads();
    if (w == 0) {
        float r = (lane < 8) ? sred[lane] : 0.0f;
#pragma unroll
        for (int o = 4; o > 0; o >>= 1) r += __shfl_down_sync(mask, r, o);
        if (lane == 0) sred[8] = r;
    }
    __syncthreads();
    return sred[8];
}

__global__ void __launch_bounds__(256) topk_kernel() {
    __shared__ unsigned int sc[256];
    __shared__ unsigned int sh_dig, sh_below;
    __shared__ float sredf[9];
    __shared__ float smu;

    const int tid = threadIdx.x;
    const int b   = blockIdx.x;
    const float* fx = g_fx + (size_t)b * CEM_S;
    const float* yy = g_y  + (size_t)b * CEM_S;

    unsigned int uk[4];
    float yv[4];
    const int i0 = tid * 4;
#pragma unroll
    for (int e = 0; e < 4; e++) {
        int i = i0 + e;
        if (i < CEM_S) { uk[e] = __float_as_uint(fx[i]); yv[e] = yy[i]; }
        else           { uk[e] = 0xFFFFFFFFu; yv[e] = 0.0f; }   // padding > any finite key
    }

    unsigned int pref = 0;
    int kRem = CEM_NE;

#pragma unroll
    for (int p = 24; p >= 0; p -= 8) {
        sc[tid] = 0u;
        __syncthreads();
#pragma unroll
        for (int e = 0; e < 4; e++) {
            bool act = (p == 24) || ((uk[e] >> (p + 8)) == pref);
            if (act) atomicAdd(&sc[(uk[e] >> p) & 0xFFu], 1u);
        }
        __syncthreads();
        for (int off = 1; off < 256; off <<= 1) {
            unsigned int add = (tid >= off) ? sc[tid - off] : 0u;
            __syncthreads();
            sc[tid] += add;
            __syncthreads();
        }
        unsigned int cum  = sc[tid];
        unsigned int prev = (tid == 0) ? 0u : sc[tid - 1];
        if (cum >= (unsigned)kRem && prev < (unsigned)kRem) { sh_dig = (unsigned)tid; sh_below = prev; }
        __syncthreads();
        pref = (pref << 8) | sh_dig;
        kRem -= (int)sh_below;
        __syncthreads();
    }
    const unsigned int T = pref;
    const int r = kRem;

    unsigned int eqc = 0;
#pragma unroll
    for (int e = 0; e < 4; e++) eqc += (uk[e] == T);
    sc[tid] = eqc;
    __syncthreads();
    for (int off = 1; off < 256; off <<= 1) {
        unsigned int add = (tid >= off) ? sc[tid - off] : 0u;
        __syncthreads();
        sc[tid] += add;
        __syncthreads();
    }
    const unsigned int baseEq = sc[tid] - eqc;

    float sum = 0.0f;
    {
        unsigned int o = 0;
#pragma unroll
        for (int e = 0; e < 4; e++) {
            bool isEq = (uk[e] == T);
            bool sel  = (uk[e] < T) || (isEq && (baseEq + o) < (unsigned)r);
            if (isEq) o++;
            if (sel) sum += yv[e];
        }
    }
    float tot = block_reduce_256(sum, sredf);
    if (tid == 0) smu = tot / (float)CEM_NE;
    __syncthreads();
    const float mu = smu;

    float ss = 0.0f;
    {
        unsigned int o = 0;
#pragma unroll
        for (int e = 0; e < 4; e++) {
            bool isEq = (uk[e] == T);
            bool sel  = (uk[e] < T) || (isEq && (baseEq + o) < (unsigned)r);
            if (isEq) o++;
            if (sel) { float d = yv[e] - mu; ss = fmaf(d, d, ss); }
        }
    }
    float sst = block_reduce_256(ss, sredf);
    if (tid == 0) {
        g_mu[b]    = mu;
        g_sigma[b] = sqrtf(sst / (float)CEM_NE);
    }
}

// ---------------- final: yhat + diag-Gaussian samples ----------------
__global__ void sample_kernel(uint32_t k0, uint32_t k1, float* __restrict__ out) {
    int gid = blockIdx.x * blockDim.x + threadIdx.x;
    if (gid >= TOTAL) return;
    int b = gid & (NBATCH - 1);
    float eps = bits_to_normal(tf_bits32(k0, k1, (uint32_t)gid));
    float mu = g_mu[b], sg = g_sigma[b];
    float cov = sg * sg;
    cov = fminf(fmaxf(cov, 1e-3f), 100.0f);
    out[NBATCH + gid] = mu + sqrtf(cov) * eps;
    if (gid < NBATCH) out[gid] = g_mu[gid];
}

// ---------------- launch ----------------
extern "C" void kernel_launch(void* const* d_in, const int* in_sizes, int n_in,
                              void* d_out, int out_size)
{
    const float* x  = (const float*)d_in[0];
    const float* W1 = (const float*)d_in[1];
    const float* b1 = (const float*)d_in[2];
    const float* W2 = (const float*)d_in[3];
    const float* b2 = (const float*)d_in[4];
    const float* W3 = (const float*)d_in[5];
    const float* b3 = (const float*)d_in[6];
    float* out = (float*)d_out;

    // JAX partitionable-mode key derivation
    uint32_t cem0 = 0u, cem1 = 0u; threefry2x32(0u, 42u, cem0, cem1);   // split(key,2)[0]
    uint32_t smp0 = 0u, smp1 = 1u; threefry2x32(0u, 42u, smp0, smp1);   // split(key,2)[1]

    uint32_t ik0[CEM_NI], ik1[CEM_NI];
    for (int i = 0; i < CEM_NI; i++) {
        uint32_t a = 0u, c = (uint32_t)i;
        threefry2x32(cem0, cem1, a, c);
        ik0[i] = a; ik1[i] = c;
    }

    const int SMEM_BYTES = 8 * 16 * 32 * (int)sizeof(uint4);   // 65,536 B
    cudaFuncSetAttribute(energy_kernel, cudaFuncAttributeMaxDynamicSharedMemorySize, SMEM_BYTES);

    w2prep_kernel<<<(8 * 16 * 32 + 255) / 256, 256>>>(W2);
    init_kernel<<<(NBATCH + 255) / 256, 256>>>();

    for (int i = 0; i < CEM_NI; i++) {
        energy_kernel<<<TOTAL / 128, 256, SMEM_BYTES>>>(ik0[i], ik1[i], x, W1, b1, b2, W3, b3);
        topk_kernel<<<NBATCH, 256>>>();
    }

    sample_kernel<<<(TOTAL + 255) / 256, 256>>>(smp0, smp1, out);
}